// round 12
// baseline (speedup 1.0000x reference)
#include <cuda_runtime.h>
#include <cuda_fp16.h>
#include <mma.h>
#include <cstdint>

using namespace nvcuda;

#define TT 2048
#define EE 1024
#define HSZ 128
#define MROWS 65536
#define NBATCH 32
// SCALE * log2(e): exp(s) == exp2(s_scaled) with this folded in
#define QSCALE 0.1275225094418865f

// Q/K/V scratch in half (Q pre-scaled by SCALE*log2e).
__device__ __half g_Q[(size_t)MROWS * HSZ];
__device__ __half g_K[(size_t)MROWS * HSZ];
__device__ __half g_V[(size_t)MROWS * HSZ];
// pre-converted weights, [w][e][hs] half, Wq pre-scaled
__device__ __half g_Wh[3 * EE * HSZ];

__device__ __forceinline__ uint32_t smem_u32(const void* p) {
    uint32_t a;
    asm("{ .reg .u64 t; cvta.to.shared.u64 t, %1; cvt.u32.u64 %0, t; }"
        : "=r"(a) : "l"(p));
    return a;
}
__device__ __forceinline__ void cp16(uint32_t dst, const void* src) {
    asm volatile("cp.async.cg.shared.global [%0], [%1], 16;"
                 :: "r"(dst), "l"(src) : "memory");
}
#define CP_COMMIT() asm volatile("cp.async.commit_group;" ::: "memory")
#define CP_WAIT(n)  asm volatile("cp.async.wait_group %0;" :: "n"(n) : "memory")
#define PAIR_BAR(id) \
    asm volatile("bar.sync %0, 64;" :: "r"(id) : "memory")

__device__ __forceinline__ float fexp2(float x) {
    float r;
    asm("ex2.approx.f32 %0, %1;" : "=f"(r) : "f"(x));
    return r;
}
__device__ __forceinline__ void mma16816(float* c, const uint32_t* a,
                                         const uint32_t* b) {
    asm volatile("mma.sync.aligned.m16n8k16.row.col.f32.f16.f16.f32 "
        "{%0,%1,%2,%3}, {%4,%5,%6,%7}, {%8,%9}, {%0,%1,%2,%3};"
        : "+f"(c[0]), "+f"(c[1]), "+f"(c[2]), "+f"(c[3])
        : "r"(a[0]), "r"(a[1]), "r"(a[2]), "r"(a[3]),
          "r"(b[0]), "r"(b[1]));
}
__device__ __forceinline__ void ldsm_x4(uint32_t* r, uint32_t a) {
    asm volatile("ldmatrix.sync.aligned.m8n8.x4.shared.b16 {%0,%1,%2,%3}, [%4];"
        : "=r"(r[0]), "=r"(r[1]), "=r"(r[2]), "=r"(r[3]) : "r"(a));
}
__device__ __forceinline__ void ldsm_x4_t(uint32_t* r, uint32_t a) {
    asm volatile("ldmatrix.sync.aligned.m8n8.x4.trans.shared.b16 {%0,%1,%2,%3}, [%4];"
        : "=r"(r[0]), "=r"(r[1]), "=r"(r[2]), "=r"(r[3]) : "r"(a));
}

// ============================================================================
// Pre-kernel: convert Wk/Wq/Wv fp32 -> g_Wh half, folding QSCALE into Wq.
// 49152 threads, 8 elements each.
// ============================================================================
__global__ void __launch_bounds__(256) wconv_kernel(
    const float* __restrict__ Wk, const float* __restrict__ Wq,
    const float* __restrict__ Wv)
{
    const int t = blockIdx.x * 256 + threadIdx.x;   // 0..49151
    const int w = t >> 14;                          // 16384 threads/weight
    const int off = (t & 16383) * 8;
    const float* src = (w == 0) ? Wk : ((w == 1) ? Wq : Wv);
    const float sc = (w == 1) ? QSCALE : 1.0f;
    float4 a = *(const float4*)(src + off);
    float4 b = *(const float4*)(src + off + 4);
    union { uint4 q; __half2 h[4]; } o;
    o.h[0] = __floats2half2_rn(a.x * sc, a.y * sc);
    o.h[1] = __floats2half2_rn(a.z * sc, a.w * sc);
    o.h[2] = __floats2half2_rn(b.x * sc, b.y * sc);
    o.h[3] = __floats2half2_rn(b.z * sc, b.w * sc);
    *(uint4*)(g_Wh + (size_t)w * (EE * HSZ) + off) = o.q;
}

// ============================================================================
// Fused projection v2: grid 1024, m-tile 64, all 3 weights per CTA (N=384).
// X staged via register-prefetch + cvt; W via cp.async from g_Wh.
// 8 warps: warp_m = wid&1 (32 rows), warp_n = wid>>1 (96 cols = 6 n16 tiles).
// smem: Xs[2][64][40]h @0 (10240 B), Ws[2][3][32][136]h @10240 (52224 B),
//       scr 8x[16][20]f @62464 (10240 B). total 72704.
// ============================================================================
#define PJ_XS(b)     ((b) * 5120)
#define PJ_WS(b, w)  (10240 + ((b) * 3 + (w)) * 8704)
#define PJ_SCR       62464
#define PJ_SMEM      72704

__global__ void __launch_bounds__(256) proj_kernel(
    const float* __restrict__ xh, const float* __restrict__ xb)
{
    extern __shared__ __align__(16) char sm[];
    const uint32_t sa = smem_u32(sm);
    const int tid = threadIdx.x, wid = tid >> 5, lane = tid & 31;
    const int warp_m = wid & 1, warp_n = wid >> 1;
    const int m0 = blockIdx.x * 64;
    const float* X = (m0 < MROWS / 2) ? xh + (size_t)m0 * EE
                                      : xb + (size_t)(m0 - MROWS / 2) * EE;
    __half* outs0 = g_K;  // w=0
    __half* outs1 = g_Q;  // w=1 (scale already folded into g_Wh)
    __half* outs2 = g_V;  // w=2
    float* scrW = (float*)(sm + PJ_SCR + wid * 1280);   // [16][20]

    // thread->element maps
    const int rX = tid >> 3, cX4 = (tid & 7);           // X: 2 iters of 256
    // W cp: 6 iters of 256: idx -> w (idx>>9), row (idx>>4)&31, c16 idx&15

    // ---- stage chunk 0 ----
    #pragma unroll
    for (int t = 0; t < 2; t++) {
        int idx = tid + t * 256, r = idx >> 3, c4 = idx & 7;
        float4 v = *(const float4*)&X[(size_t)r * EE + c4 * 4];
        __half* d = (__half*)(sm + PJ_XS(0)) + r * 40 + c4 * 4;
        *(__half2*)d       = __floats2half2_rn(v.x, v.y);
        *(__half2*)(d + 2) = __floats2half2_rn(v.z, v.w);
    }
    #pragma unroll
    for (int t = 0; t < 6; t++) {
        int idx = tid + t * 256;
        int w = idx >> 9, rr = (idx >> 4) & 31, c16 = idx & 15;
        cp16(sa + PJ_WS(0, w) + rr * 272 + c16 * 16,
             (const char*)(g_Wh + (size_t)w * (EE * HSZ) + rr * HSZ) + c16 * 16);
    }
    CP_COMMIT();

    wmma::fragment<wmma::accumulator, 16, 16, 16, float> acc[2][6];
    #pragma unroll
    for (int i = 0; i < 2; i++)
        #pragma unroll
        for (int j = 0; j < 6; j++)
            wmma::fill_fragment(acc[i][j], 0.0f);

    for (int c = 0; c < 32; c++) {
        const int b = c & 1;
        CP_WAIT(0);
        __syncthreads();

        float4 px[2];
        if (c + 1 < 32) {
            #pragma unroll
            for (int t = 0; t < 2; t++) {
                int idx = tid + t * 256, r = idx >> 3, c4 = idx & 7;
                px[t] = *(const float4*)&X[(size_t)r * EE + (c + 1) * 32 + c4 * 4];
            }
            #pragma unroll
            for (int t = 0; t < 6; t++) {
                int idx = tid + t * 256;
                int w = idx >> 9, rr = (idx >> 4) & 31, c16 = idx & 15;
                cp16(sa + PJ_WS(b ^ 1, w) + rr * 272 + c16 * 16,
                     (const char*)(g_Wh + (size_t)w * (EE * HSZ) +
                                   (size_t)((c + 1) * 32 + rr) * HSZ) + c16 * 16);
            }
            CP_COMMIT();
        }

        const __half* Xs = (const __half*)(sm + PJ_XS(b));
        #pragma unroll
        for (int kk = 0; kk < 32; kk += 16) {
            wmma::fragment<wmma::matrix_a, 16, 16, 16, __half,
                           wmma::row_major> a[2];
            #pragma unroll
            for (int i = 0; i < 2; i++)
                wmma::load_matrix_sync(a[i],
                    Xs + (warp_m * 32 + i * 16) * 40 + kk, 40);
            #pragma unroll
            for (int j = 0; j < 6; j++) {
                const int gc = warp_n * 96 + j * 16;
                const int w = gc >> 7, col = gc & 127;
                const __half* Wsb = (const __half*)(sm + PJ_WS(b, w));
                wmma::fragment<wmma::matrix_b, 16, 16, 16, __half,
                               wmma::row_major> bf;
                wmma::load_matrix_sync(bf, Wsb + kk * 136 + col, 136);
                #pragma unroll
                for (int i = 0; i < 2; i++)
                    wmma::mma_sync(acc[i][j], a[i], bf, acc[i][j]);
            }
        }

        if (c + 1 < 32) {
            #pragma unroll
            for (int t = 0; t < 2; t++) {
                int idx = tid + t * 256, r = idx >> 3, c4 = idx & 7;
                __half* d = (__half*)(sm + PJ_XS(b ^ 1)) + r * 40 + c4 * 4;
                *(__half2*)d       = __floats2half2_rn(px[t].x, px[t].y);
                *(__half2*)(d + 2) = __floats2half2_rn(px[t].z, px[t].w);
            }
        }
    }

    // ---- epilogue: acc -> half outputs via per-warp scratch ----
    const int row = lane >> 1, c0 = (lane & 1) * 8;
    #pragma unroll
    for (int i = 0; i < 2; i++)
        #pragma unroll
        for (int j = 0; j < 6; j++) {
            __syncwarp();
            wmma::store_matrix_sync(scrW, acc[i][j], 20, wmma::mem_row_major);
            __syncwarp();
            float4 u = *(float4*)&scrW[row * 20 + c0];
            float4 v = *(float4*)&scrW[row * 20 + c0 + 4];
            union { uint4 q; __half2 h[4]; } o;
            o.h[0] = __floats2half2_rn(u.x, u.y);
            o.h[1] = __floats2half2_rn(u.z, u.w);
            o.h[2] = __floats2half2_rn(v.x, v.y);
            o.h[3] = __floats2half2_rn(v.z, v.w);
            const int gc = warp_n * 96 + j * 16;
            const int w = gc >> 7, col = (gc & 127) + c0;
            const int gm = m0 + warp_m * 32 + i * 16 + row;
            __half* Out = (w == 0) ? outs0 : ((w == 1) ? outs1 : outs2);
            *(uint4*)&Out[(size_t)gm * HSZ + col] = o.q;
        }
}

// ============================================================================
// Fused flash attention v4 (unchanged from R11): raw mma.m16n8k16, 256 thr.
// ============================================================================
#define SM_K(b) ((b) * 17408)
#define SM_V(b) (34816 + (b) * 17408)
#define SM_PH   69632
#define SM_LP   88064
#define A_SMEM  89088

__global__ void __launch_bounds__(256) attn_kernel(float* __restrict__ out)
{
    extern __shared__ __align__(16) char sm[];
    const uint32_t sa = smem_u32(sm);
    const uint32_t ph = sa + SM_PH;
    float* smLp = (float*)(sm + SM_LP);
    const int tid = threadIdx.x, wid = tid >> 5, lane = tid & 31;
    const int warp_m = wid & 3, warp_n = wid >> 2;
    const int tg = lane >> 2, tq = lane & 3;
    const int sb = blockIdx.y, q0 = blockIdx.x * 128;
    const __half* Qg = g_Q + ((size_t)sb * TT + q0) * HSZ;
    const __half* Kg = g_K + (size_t)sb * TT * HSZ;
    const __half* Vg = g_V + (size_t)sb * TT * HSZ;

    #pragma unroll
    for (int t = 0; t < 4; t++) {
        int idx = tid + t * 256, r = idx >> 4, c16 = idx & 15;
        cp16(sa + SM_K(0) + r * 272 + c16 * 16,
             (const char*)Kg + (size_t)r * 256 + c16 * 16);
        cp16(sa + SM_V(0) + r * 272 + c16 * 16,
             (const char*)Vg + (size_t)r * 256 + c16 * 16);
    }
    CP_COMMIT();

    uint32_t aq[2][8][4];
    #pragma unroll
    for (int i = 0; i < 2; i++)
        #pragma unroll
        for (int k = 0; k < 8; k++) {
            const __half* p = Qg + (size_t)(warp_m * 32 + i * 16 + tg) * HSZ +
                              k * 16 + tq * 2;
            aq[i][k][0] = *(const uint32_t*)p;
            aq[i][k][1] = *(const uint32_t*)(p + 8 * HSZ);
            aq[i][k][2] = *(const uint32_t*)(p + 8);
            aq[i][k][3] = *(const uint32_t*)(p + 8 * HSZ + 8);
        }

    float acc_o[2][8][4];
    #pragma unroll
    for (int i = 0; i < 2; i++)
        #pragma unroll
        for (int j = 0; j < 8; j++)
            #pragma unroll
            for (int e = 0; e < 4; e++)
                acc_o[i][j][e] = 0.0f;
    float Lc[4] = { 0.0f, 0.0f, 0.0f, 0.0f };

    const int l8 = lane & 7, sel = lane >> 3;
    const uint32_t koff = (uint32_t)((l8 + ((sel >> 1) & 1) * 8) * 272 +
                                     (sel & 1) * 16);
    const uint32_t voff = (uint32_t)((l8 + (sel & 1) * 8) * 272 +
                                     ((sel >> 1) & 1) * 16);
    const uint32_t poff = (uint32_t)((l8 + (sel & 1) * 8) * 144 +
                                     ((sel >> 1) & 1) * 16);

    for (int c = 0; c < 32; c++) {
        CP_WAIT(0);
        __syncthreads();
        if (c + 1 < 32) {
            const char* Kc = (const char*)Kg + (size_t)(c + 1) * 64 * 256;
            const char* Vc = (const char*)Vg + (size_t)(c + 1) * 64 * 256;
            #pragma unroll
            for (int t = 0; t < 4; t++) {
                int idx = tid + t * 256, r = idx >> 4, c16 = idx & 15;
                cp16(sa + SM_K((c + 1) & 1) + r * 272 + c16 * 16,
                     Kc + (size_t)r * 256 + c16 * 16);
                cp16(sa + SM_V((c + 1) & 1) + r * 272 + c16 * 16,
                     Vc + (size_t)r * 256 + c16 * 16);
            }
            CP_COMMIT();
        }
        const uint32_t kb = sa + SM_K(c & 1);
        const uint32_t vb = sa + SM_V(c & 1);

        float acc_s[2][4][4];
        #pragma unroll
        for (int i = 0; i < 2; i++)
            #pragma unroll
            for (int j = 0; j < 4; j++)
                #pragma unroll
                for (int e = 0; e < 4; e++)
                    acc_s[i][j][e] = 0.0f;
        #pragma unroll
        for (int k = 0; k < 8; k++) {
            uint32_t bk[8];
            ldsm_x4(bk,     kb + (warp_n * 32) * 272 + k * 32 + koff);
            ldsm_x4(bk + 4, kb + (warp_n * 32 + 16) * 272 + k * 32 + koff);
            #pragma unroll
            for (int i = 0; i < 2; i++)
                #pragma unroll
                for (int j = 0; j < 4; j++)
                    mma16816(acc_s[i][j], aq[i][k], &bk[j * 2]);
        }

        uint32_t ap[2][2][4];
        #pragma unroll
        for (int i = 0; i < 2; i++)
            #pragma unroll
            for (int j = 0; j < 4; j++) {
                __half2 h0 = __floats2half2_rn(fexp2(acc_s[i][j][0]),
                                               fexp2(acc_s[i][j][1]));
                __half2 h1 = __floats2half2_rn(fexp2(acc_s[i][j][2]),
                                               fexp2(acc_s[i][j][3]));
                float2 f0 = __half22float2(h0);
                float2 f1 = __half22float2(h1);
                Lc[i * 2 + 0] += f0.x + f0.y;
                Lc[i * 2 + 1] += f1.x + f1.y;
                ap[i][j >> 1][(j & 1) * 2 + 0] = *(uint32_t*)&h0;
                ap[i][j >> 1][(j & 1) * 2 + 1] = *(uint32_t*)&h1;
            }

        PAIR_BAR(1 + warp_m);

        #pragma unroll
        for (int i = 0; i < 2; i++)
            #pragma unroll
            for (int j = 0; j < 4; j++) {
                uint32_t addr = ph + (uint32_t)(warp_m * 32 + i * 16 + tg) * 144 +
                                (uint32_t)(warp_n * 32 + j * 8 + tq * 2) * 2;
                asm volatile("st.shared.b32 [%0], %1;"
                             :: "r"(addr), "r"(ap[i][j >> 1][(j & 1) * 2]));
                asm volatile("st.shared.b32 [%0], %1;"
                             :: "r"(addr + 8 * 144),
                                "r"(ap[i][j >> 1][(j & 1) * 2 + 1]));
            }

        PAIR_BAR(1 + warp_m);

        #pragma unroll
        for (int s = 0; s < 4; s++) {
            uint32_t av[2][4];
            if ((s >> 1) == warp_n) {
                #pragma unroll
                for (int i = 0; i < 2; i++)
                    #pragma unroll
                    for (int e = 0; e < 4; e++)
                        av[i][e] = ap[i][s & 1][e];
            } else {
                #pragma unroll
                for (int i = 0; i < 2; i++)
                    ldsm_x4(av[i], ph + (uint32_t)(warp_m * 32 + i * 16) * 144 +
                                   s * 32 + poff);
            }
            #pragma unroll
            for (int jj = 0; jj < 4; jj++) {
                uint32_t bv[4];
                ldsm_x4_t(bv, vb + (s * 16) * 272 +
                              (warp_n * 64 + jj * 16) * 2 + voff);
                #pragma unroll
                for (int i = 0; i < 2; i++) {
                    mma16816(acc_o[i][jj * 2],     av[i], bv);
                    mma16816(acc_o[i][jj * 2 + 1], av[i], bv + 2);
                }
            }
        }
    }

    #pragma unroll
    for (int q = 0; q < 4; q++) {
        Lc[q] += __shfl_xor_sync(0xffffffffu, Lc[q], 1);
        Lc[q] += __shfl_xor_sync(0xffffffffu, Lc[q], 2);
    }
    if (tq == 0) {
        #pragma unroll
        for (int i = 0; i < 2; i++)
            #pragma unroll
            for (int h = 0; h < 2; h++)
                smLp[(warp_m * 32 + i * 16 + h * 8 + tg) * 2 + warp_n] =
                    Lc[i * 2 + h];
    }
    __syncthreads();

    #pragma unroll
    for (int i = 0; i < 2; i++) {
        const int r0 = warp_m * 32 + i * 16 + tg;
        const float inv0 = 1.0f / (smLp[r0 * 2] + smLp[r0 * 2 + 1]);
        const float inv1 = 1.0f / (smLp[(r0 + 8) * 2] + smLp[(r0 + 8) * 2 + 1]);
        float* O0 = out + ((size_t)sb * TT + q0 + r0) * HSZ + warp_n * 64 + tq * 2;
        float* O1 = O0 + 8 * HSZ;
        #pragma unroll
        for (int j = 0; j < 8; j++) {
            float2 v0 = { acc_o[i][j][0] * inv0, acc_o[i][j][1] * inv0 };
            float2 v1 = { acc_o[i][j][2] * inv1, acc_o[i][j][3] * inv1 };
            *(float2*)(O0 + j * 8) = v0;
            *(float2*)(O1 + j * 8) = v1;
        }
    }
}

// ============================================================================
extern "C" void kernel_launch(void* const* d_in, const int* in_sizes, int n_in,
                              void* d_out, int out_size)
{
    const float* x_head = (const float*)d_in[0];
    const float* x_body = (const float*)d_in[1];
    const float* Wk     = (const float*)d_in[2];
    const float* Wq     = (const float*)d_in[3];
    const float* Wv     = (const float*)d_in[4];
    float* out = (float*)d_out;

    cudaFuncSetAttribute(proj_kernel,
                         cudaFuncAttributeMaxDynamicSharedMemorySize, PJ_SMEM);
    cudaFuncSetAttribute(attn_kernel,
                         cudaFuncAttributeMaxDynamicSharedMemorySize, A_SMEM);

    wconv_kernel<<<192, 256>>>(Wk, Wq, Wv);
    proj_kernel<<<dim3(MROWS / 64, 1, 1), 256, PJ_SMEM>>>(x_head, x_body);
    attn_kernel<<<dim3(TT / 128, NBATCH, 1), 256, A_SMEM>>>(out);
}

// round 13
// speedup vs baseline: 1.0666x; 1.0666x over previous
#include <cuda_runtime.h>
#include <cuda_fp16.h>
#include <mma.h>
#include <cstdint>

using namespace nvcuda;

#define TT 2048
#define EE 1024
#define HSZ 128
#define MROWS 65536
#define NBATCH 32
// SCALE * log2(e): exp(s) == exp2(s_scaled) with this folded in
#define QSCALE 0.1275225094418865f

// Q/K/V scratch in half (Q pre-scaled by SCALE*log2e via g_Wh).
__device__ __half g_Q[(size_t)MROWS * HSZ];
__device__ __half g_K[(size_t)MROWS * HSZ];
__device__ __half g_V[(size_t)MROWS * HSZ];
// pre-converted weights, [w][e][hs] half, Wq pre-scaled
__device__ __half g_Wh[3 * EE * HSZ];

__device__ __forceinline__ uint32_t smem_u32(const void* p) {
    uint32_t a;
    asm("{ .reg .u64 t; cvta.to.shared.u64 t, %1; cvt.u32.u64 %0, t; }"
        : "=r"(a) : "l"(p));
    return a;
}
__device__ __forceinline__ void cp16(uint32_t dst, const void* src) {
    asm volatile("cp.async.cg.shared.global [%0], [%1], 16;"
                 :: "r"(dst), "l"(src) : "memory");
}
#define CP_COMMIT() asm volatile("cp.async.commit_group;" ::: "memory")
#define CP_WAIT(n)  asm volatile("cp.async.wait_group %0;" :: "n"(n) : "memory")
#define PAIR_BAR(id) \
    asm volatile("bar.sync %0, 64;" :: "r"(id) : "memory")

__device__ __forceinline__ float fexp2(float x) {
    float r;
    asm("ex2.approx.f32 %0, %1;" : "=f"(r) : "f"(x));
    return r;
}
__device__ __forceinline__ void mma16816(float* c, const uint32_t* a,
                                         const uint32_t* b) {
    asm volatile("mma.sync.aligned.m16n8k16.row.col.f32.f16.f16.f32 "
        "{%0,%1,%2,%3}, {%4,%5,%6,%7}, {%8,%9}, {%0,%1,%2,%3};"
        : "+f"(c[0]), "+f"(c[1]), "+f"(c[2]), "+f"(c[3])
        : "r"(a[0]), "r"(a[1]), "r"(a[2]), "r"(a[3]),
          "r"(b[0]), "r"(b[1]));
}
__device__ __forceinline__ void ldsm_x4(uint32_t* r, uint32_t a) {
    asm volatile("ldmatrix.sync.aligned.m8n8.x4.shared.b16 {%0,%1,%2,%3}, [%4];"
        : "=r"(r[0]), "=r"(r[1]), "=r"(r[2]), "=r"(r[3]) : "r"(a));
}
__device__ __forceinline__ void ldsm_x4_t(uint32_t* r, uint32_t a) {
    asm volatile("ldmatrix.sync.aligned.m8n8.x4.trans.shared.b16 {%0,%1,%2,%3}, [%4];"
        : "=r"(r[0]), "=r"(r[1]), "=r"(r[2]), "=r"(r[3]) : "r"(a));
}

// ============================================================================
// Pre-kernel: convert Wk/Wq/Wv fp32 -> g_Wh half, folding QSCALE into Wq.
// ============================================================================
__global__ void __launch_bounds__(256) wconv_kernel(
    const float* __restrict__ Wk, const float* __restrict__ Wq,
    const float* __restrict__ Wv)
{
    const int t = blockIdx.x * 256 + threadIdx.x;   // 0..49151
    const int w = t >> 14;
    const int off = (t & 16383) * 8;
    const float* src = (w == 0) ? Wk : ((w == 1) ? Wq : Wv);
    const float sc = (w == 1) ? QSCALE : 1.0f;
    float4 a = *(const float4*)(src + off);
    float4 b = *(const float4*)(src + off + 4);
    union { uint4 q; __half2 h[4]; } o;
    o.h[0] = __floats2half2_rn(a.x * sc, a.y * sc);
    o.h[1] = __floats2half2_rn(a.z * sc, a.w * sc);
    o.h[2] = __floats2half2_rn(b.x * sc, b.y * sc);
    o.h[3] = __floats2half2_rn(b.z * sc, b.w * sc);
    *(uint4*)(g_Wh + (size_t)w * (EE * HSZ) + off) = o.q;
}

// ============================================================================
// Projection v3: R11 shape (BM=128, grid (512,3)) with half-W via cp.async.
// 8 warps: warp_m = wid&3 (32 rows), warp_n = wid>>2 (64 cols).
// One __syncthreads + one cp.async.wait per K-chunk; X register-prefetched.
// ============================================================================
__global__ void __launch_bounds__(256) proj_kernel(
    const float* __restrict__ xh, const float* __restrict__ xb)
{
    __shared__ __align__(16) __half As[2][128][40];
    __shared__ __align__(16) __half Ws[2][32][136];
    __shared__ __align__(16) float  scr[8][16][20];

    const int m0 = blockIdx.x * 128;
    const int w  = blockIdx.y;
    const float* X = (m0 < MROWS / 2) ? xh + (size_t)m0 * EE
                                      : xb + (size_t)(m0 - MROWS / 2) * EE;
    const __half* Wg = g_Wh + (size_t)w * (EE * HSZ);
    __half* Out = (w == 0) ? g_K : ((w == 1) ? g_Q : g_V);

    const int tid = threadIdx.x, wid = tid >> 5, lane = tid & 31;
    const int warp_m = wid & 3, warp_n = wid >> 2;
    const uint32_t wsa0 = smem_u32(&Ws[0][0][0]);
    const uint32_t wsa1 = smem_u32(&Ws[1][0][0]);

    wmma::fragment<wmma::accumulator, 16, 16, 16, float> acc[2][4];
    #pragma unroll
    for (int i = 0; i < 2; i++)
        #pragma unroll
        for (int j = 0; j < 4; j++)
            wmma::fill_fragment(acc[i][j], 0.0f);

    const int rX = tid >> 3,  cX = (tid & 7) * 4;    // X: 4 iters, +32 rows
    const int rW = tid >> 4,  cW16 = (tid & 15);     // W: 2 iters, +16 rows

    // stage chunk 0: X (cvt in regs), W (cp.async)
    #pragma unroll
    for (int i = 0; i < 4; i++) {
        float4 v = *(const float4*)&X[(size_t)(rX + i * 32) * EE + cX];
        __half2* d = (__half2*)&As[0][rX + i * 32][cX];
        d[0] = __floats2half2_rn(v.x, v.y);
        d[1] = __floats2half2_rn(v.z, v.w);
    }
    #pragma unroll
    for (int i = 0; i < 2; i++)
        cp16(wsa0 + (rW + i * 16) * 272 + cW16 * 16,
             (const char*)(Wg + (size_t)(rW + i * 16) * HSZ) + cW16 * 16);
    CP_COMMIT();

    for (int c = 0; c < 32; c++) {
        const int b = c & 1;
        CP_WAIT(0);
        __syncthreads();      // W(c) arrived; X(c) stored; As[b^1] readers done

        float4 px[4];
        if (c + 1 < 32) {
            #pragma unroll
            for (int i = 0; i < 4; i++)
                px[i] = *(const float4*)&X[(size_t)(rX + i * 32) * EE +
                                           (c + 1) * 32 + cX];
            const uint32_t wdst = b ? wsa0 : wsa1;
            #pragma unroll
            for (int i = 0; i < 2; i++)
                cp16(wdst + (rW + i * 16) * 272 + cW16 * 16,
                     (const char*)(Wg + (size_t)((c + 1) * 32 + rW + i * 16) *
                                   HSZ) + cW16 * 16);
            CP_COMMIT();
        }

        #pragma unroll
        for (int kk = 0; kk < 32; kk += 16) {
            wmma::fragment<wmma::matrix_a, 16, 16, 16, __half,
                           wmma::row_major> a[2];
            wmma::fragment<wmma::matrix_b, 16, 16, 16, __half,
                           wmma::row_major> bf[4];
            #pragma unroll
            for (int i = 0; i < 2; i++)
                wmma::load_matrix_sync(a[i], &As[b][warp_m * 32 + i * 16][kk], 40);
            #pragma unroll
            for (int j = 0; j < 4; j++)
                wmma::load_matrix_sync(bf[j], &Ws[b][kk][warp_n * 64 + j * 16], 136);
            #pragma unroll
            for (int i = 0; i < 2; i++)
                #pragma unroll
                for (int j = 0; j < 4; j++)
                    wmma::mma_sync(acc[i][j], a[i], bf[j], acc[i][j]);
        }

        if (c + 1 < 32) {     // store prefetched X into other buffer
            const int nb = (c + 1) & 1;
            #pragma unroll
            for (int i = 0; i < 4; i++) {
                __half2* d = (__half2*)&As[nb][rX + i * 32][cX];
                d[0] = __floats2half2_rn(px[i].x, px[i].y);
                d[1] = __floats2half2_rn(px[i].z, px[i].w);
            }
        }
    }

    // epilogue: acc -> half gmem via per-warp scratch (scale pre-folded)
    const int row = lane >> 1, c0 = (lane & 1) * 8;
    #pragma unroll
    for (int i = 0; i < 2; i++)
        #pragma unroll
        for (int j = 0; j < 4; j++) {
            __syncwarp();
            wmma::store_matrix_sync(&scr[wid][0][0], acc[i][j], 20,
                                    wmma::mem_row_major);
            __syncwarp();
            float4 u = *(float4*)&scr[wid][row][c0];
            float4 v = *(float4*)&scr[wid][row][c0 + 4];
            union { uint4 q; __half2 h[4]; } o;
            o.h[0] = __floats2half2_rn(u.x, u.y);
            o.h[1] = __floats2half2_rn(u.z, u.w);
            o.h[2] = __floats2half2_rn(v.x, v.y);
            o.h[3] = __floats2half2_rn(v.z, v.w);
            const int gm = m0 + warp_m * 32 + i * 16 + row;
            const int gc = warp_n * 64 + j * 16 + c0;
            *(uint4*)&Out[(size_t)gm * HSZ + gc] = o.q;
        }
}

// ============================================================================
// Fused flash attention v4 (unchanged from R11): raw mma.m16n8k16, 256 thr.
// ============================================================================
#define SM_K(b) ((b) * 17408)
#define SM_V(b) (34816 + (b) * 17408)
#define SM_PH   69632
#define SM_LP   88064
#define A_SMEM  89088

__global__ void __launch_bounds__(256) attn_kernel(float* __restrict__ out)
{
    extern __shared__ __align__(16) char sm[];
    const uint32_t sa = smem_u32(sm);
    const uint32_t ph = sa + SM_PH;
    float* smLp = (float*)(sm + SM_LP);
    const int tid = threadIdx.x, wid = tid >> 5, lane = tid & 31;
    const int warp_m = wid & 3, warp_n = wid >> 2;
    const int tg = lane >> 2, tq = lane & 3;
    const int sb = blockIdx.y, q0 = blockIdx.x * 128;
    const __half* Qg = g_Q + ((size_t)sb * TT + q0) * HSZ;
    const __half* Kg = g_K + (size_t)sb * TT * HSZ;
    const __half* Vg = g_V + (size_t)sb * TT * HSZ;

    #pragma unroll
    for (int t = 0; t < 4; t++) {
        int idx = tid + t * 256, r = idx >> 4, c16 = idx & 15;
        cp16(sa + SM_K(0) + r * 272 + c16 * 16,
             (const char*)Kg + (size_t)r * 256 + c16 * 16);
        cp16(sa + SM_V(0) + r * 272 + c16 * 16,
             (const char*)Vg + (size_t)r * 256 + c16 * 16);
    }
    CP_COMMIT();

    uint32_t aq[2][8][4];
    #pragma unroll
    for (int i = 0; i < 2; i++)
        #pragma unroll
        for (int k = 0; k < 8; k++) {
            const __half* p = Qg + (size_t)(warp_m * 32 + i * 16 + tg) * HSZ +
                              k * 16 + tq * 2;
            aq[i][k][0] = *(const uint32_t*)p;
            aq[i][k][1] = *(const uint32_t*)(p + 8 * HSZ);
            aq[i][k][2] = *(const uint32_t*)(p + 8);
            aq[i][k][3] = *(const uint32_t*)(p + 8 * HSZ + 8);
        }

    float acc_o[2][8][4];
    #pragma unroll
    for (int i = 0; i < 2; i++)
        #pragma unroll
        for (int j = 0; j < 8; j++)
            #pragma unroll
            for (int e = 0; e < 4; e++)
                acc_o[i][j][e] = 0.0f;
    float Lc[4] = { 0.0f, 0.0f, 0.0f, 0.0f };

    const int l8 = lane & 7, sel = lane >> 3;
    const uint32_t koff = (uint32_t)((l8 + ((sel >> 1) & 1) * 8) * 272 +
                                     (sel & 1) * 16);
    const uint32_t voff = (uint32_t)((l8 + (sel & 1) * 8) * 272 +
                                     ((sel >> 1) & 1) * 16);
    const uint32_t poff = (uint32_t)((l8 + (sel & 1) * 8) * 144 +
                                     ((sel >> 1) & 1) * 16);

    for (int c = 0; c < 32; c++) {
        CP_WAIT(0);
        __syncthreads();
        if (c + 1 < 32) {
            const char* Kc = (const char*)Kg + (size_t)(c + 1) * 64 * 256;
            const char* Vc = (const char*)Vg + (size_t)(c + 1) * 64 * 256;
            #pragma unroll
            for (int t = 0; t < 4; t++) {
                int idx = tid + t * 256, r = idx >> 4, c16 = idx & 15;
                cp16(sa + SM_K((c + 1) & 1) + r * 272 + c16 * 16,
                     Kc + (size_t)r * 256 + c16 * 16);
                cp16(sa + SM_V((c + 1) & 1) + r * 272 + c16 * 16,
                     Vc + (size_t)r * 256 + c16 * 16);
            }
            CP_COMMIT();
        }
        const uint32_t kb = sa + SM_K(c & 1);
        const uint32_t vb = sa + SM_V(c & 1);

        float acc_s[2][4][4];
        #pragma unroll
        for (int i = 0; i < 2; i++)
            #pragma unroll
            for (int j = 0; j < 4; j++)
                #pragma unroll
                for (int e = 0; e < 4; e++)
                    acc_s[i][j][e] = 0.0f;
        #pragma unroll
        for (int k = 0; k < 8; k++) {
            uint32_t bk[8];
            ldsm_x4(bk,     kb + (warp_n * 32) * 272 + k * 32 + koff);
            ldsm_x4(bk + 4, kb + (warp_n * 32 + 16) * 272 + k * 32 + koff);
            #pragma unroll
            for (int i = 0; i < 2; i++)
                #pragma unroll
                for (int j = 0; j < 4; j++)
                    mma16816(acc_s[i][j], aq[i][k], &bk[j * 2]);
        }

        uint32_t ap[2][2][4];
        #pragma unroll
        for (int i = 0; i < 2; i++)
            #pragma unroll
            for (int j = 0; j < 4; j++) {
                __half2 h0 = __floats2half2_rn(fexp2(acc_s[i][j][0]),
                                               fexp2(acc_s[i][j][1]));
                __half2 h1 = __floats2half2_rn(fexp2(acc_s[i][j][2]),
                                               fexp2(acc_s[i][j][3]));
                float2 f0 = __half22float2(h0);
                float2 f1 = __half22float2(h1);
                Lc[i * 2 + 0] += f0.x + f0.y;
                Lc[i * 2 + 1] += f1.x + f1.y;
                ap[i][j >> 1][(j & 1) * 2 + 0] = *(uint32_t*)&h0;
                ap[i][j >> 1][(j & 1) * 2 + 1] = *(uint32_t*)&h1;
            }

        PAIR_BAR(1 + warp_m);

        #pragma unroll
        for (int i = 0; i < 2; i++)
            #pragma unroll
            for (int j = 0; j < 4; j++) {
                uint32_t addr = ph + (uint32_t)(warp_m * 32 + i * 16 + tg) * 144 +
                                (uint32_t)(warp_n * 32 + j * 8 + tq * 2) * 2;
                asm volatile("st.shared.b32 [%0], %1;"
                             :: "r"(addr), "r"(ap[i][j >> 1][(j & 1) * 2]));
                asm volatile("st.shared.b32 [%0], %1;"
                             :: "r"(addr + 8 * 144),
                                "r"(ap[i][j >> 1][(j & 1) * 2 + 1]));
            }

        PAIR_BAR(1 + warp_m);

        #pragma unroll
        for (int s = 0; s < 4; s++) {
            uint32_t av[2][4];
            if ((s >> 1) == warp_n) {
                #pragma unroll
                for (int i = 0; i < 2; i++)
                    #pragma unroll
                    for (int e = 0; e < 4; e++)
                        av[i][e] = ap[i][s & 1][e];
            } else {
                #pragma unroll
                for (int i = 0; i < 2; i++)
                    ldsm_x4(av[i], ph + (uint32_t)(warp_m * 32 + i * 16) * 144 +
                                   s * 32 + poff);
            }
            #pragma unroll
            for (int jj = 0; jj < 4; jj++) {
                uint32_t bv[4];
                ldsm_x4_t(bv, vb + (s * 16) * 272 +
                              (warp_n * 64 + jj * 16) * 2 + voff);
                #pragma unroll
                for (int i = 0; i < 2; i++) {
                    mma16816(acc_o[i][jj * 2],     av[i], bv);
                    mma16816(acc_o[i][jj * 2 + 1], av[i], bv + 2);
                }
            }
        }
    }

    #pragma unroll
    for (int q = 0; q < 4; q++) {
        Lc[q] += __shfl_xor_sync(0xffffffffu, Lc[q], 1);
        Lc[q] += __shfl_xor_sync(0xffffffffu, Lc[q], 2);
    }
    if (tq == 0) {
        #pragma unroll
        for (int i = 0; i < 2; i++)
            #pragma unroll
            for (int h = 0; h < 2; h++)
                smLp[(warp_m * 32 + i * 16 + h * 8 + tg) * 2 + warp_n] =
                    Lc[i * 2 + h];
    }
    __syncthreads();

    #pragma unroll
    for (int i = 0; i < 2; i++) {
        const int r0 = warp_m * 32 + i * 16 + tg;
        const float inv0 = 1.0f / (smLp[r0 * 2] + smLp[r0 * 2 + 1]);
        const float inv1 = 1.0f / (smLp[(r0 + 8) * 2] + smLp[(r0 + 8) * 2 + 1]);
        float* O0 = out + ((size_t)sb * TT + q0 + r0) * HSZ + warp_n * 64 + tq * 2;
        float* O1 = O0 + 8 * HSZ;
        #pragma unroll
        for (int j = 0; j < 8; j++) {
            float2 v0 = { acc_o[i][j][0] * inv0, acc_o[i][j][1] * inv0 };
            float2 v1 = { acc_o[i][j][2] * inv1, acc_o[i][j][3] * inv1 };
            *(float2*)(O0 + j * 8) = v0;
            *(float2*)(O1 + j * 8) = v1;
        }
    }
}

// ============================================================================
extern "C" void kernel_launch(void* const* d_in, const int* in_sizes, int n_in,
                              void* d_out, int out_size)
{
    const float* x_head = (const float*)d_in[0];
    const float* x_body = (const float*)d_in[1];
    const float* Wk     = (const float*)d_in[2];
    const float* Wq     = (const float*)d_in[3];
    const float* Wv     = (const float*)d_in[4];
    float* out = (float*)d_out;

    cudaFuncSetAttribute(attn_kernel,
                         cudaFuncAttributeMaxDynamicSharedMemorySize, A_SMEM);

    wconv_kernel<<<192, 256>>>(Wk, Wq, Wv);
    proj_kernel<<<dim3(MROWS / 128, 3, 1), 256>>>(x_head, x_body);
    attn_kernel<<<dim3(TT / 128, NBATCH, 1), 256, A_SMEM>>>(out);
}

// round 14
// speedup vs baseline: 1.1645x; 1.0917x over previous
#include <cuda_runtime.h>
#include <cuda_fp16.h>
#include <mma.h>
#include <cstdint>

using namespace nvcuda;

#define TT 2048
#define EE 1024
#define HSZ 128
#define MROWS 65536
#define NBATCH 32
// SCALE * log2(e): exp(s) == exp2(s_scaled) with this folded in
#define QSCALE 0.1275225094418865f

// Q/K/V scratch in half (Q pre-scaled by SCALE*log2e).
__device__ __half g_Q[(size_t)MROWS * HSZ];
__device__ __half g_K[(size_t)MROWS * HSZ];
__device__ __half g_V[(size_t)MROWS * HSZ];

__device__ __forceinline__ uint32_t smem_u32(const void* p) {
    uint32_t a;
    asm("{ .reg .u64 t; cvta.to.shared.u64 t, %1; cvt.u32.u64 %0, t; }"
        : "=r"(a) : "l"(p));
    return a;
}
__device__ __forceinline__ void cp16(uint32_t dst, const void* src) {
    asm volatile("cp.async.cg.shared.global [%0], [%1], 16;"
                 :: "r"(dst), "l"(src) : "memory");
}
#define CP_COMMIT() asm volatile("cp.async.commit_group;" ::: "memory")
#define CP_WAIT(n)  asm volatile("cp.async.wait_group %0;" :: "n"(n) : "memory")
#define PAIR_BAR(id) \
    asm volatile("bar.sync %0, 64;" :: "r"(id) : "memory")

__device__ __forceinline__ float fexp2(float x) {
    float r;
    asm("ex2.approx.f32 %0, %1;" : "=f"(r) : "f"(x));
    return r;
}
__device__ __forceinline__ void mma16816(float* c, const uint32_t* a,
                                         const uint32_t* b) {
    asm volatile("mma.sync.aligned.m16n8k16.row.col.f32.f16.f16.f32 "
        "{%0,%1,%2,%3}, {%4,%5,%6,%7}, {%8,%9}, {%0,%1,%2,%3};"
        : "+f"(c[0]), "+f"(c[1]), "+f"(c[2]), "+f"(c[3])
        : "r"(a[0]), "r"(a[1]), "r"(a[2]), "r"(a[3]),
          "r"(b[0]), "r"(b[1]));
}
__device__ __forceinline__ void ldsm_x4(uint32_t* r, uint32_t a) {
    asm volatile("ldmatrix.sync.aligned.m8n8.x4.shared.b16 {%0,%1,%2,%3}, [%4];"
        : "=r"(r[0]), "=r"(r[1]), "=r"(r[2]), "=r"(r[3]) : "r"(a));
}
__device__ __forceinline__ void ldsm_x4_t(uint32_t* r, uint32_t a) {
    asm volatile("ldmatrix.sync.aligned.m8n8.x4.trans.shared.b16 {%0,%1,%2,%3}, [%4];"
        : "=r"(r[0]), "=r"(r[1]), "=r"(r[2]), "=r"(r[3]) : "r"(a));
}

// ============================================================================
// Projection (R11 config — the measured-best): C = X @ W, outputs half,
// grid (512, 3), 256 thr, BM=128 BK=32, X+W cvt at staging, reg prefetch.
// ============================================================================
__global__ void __launch_bounds__(256) proj_kernel(
    const float* __restrict__ xh, const float* __restrict__ xb,
    const float* __restrict__ Wk, const float* __restrict__ Wq,
    const float* __restrict__ Wv)
{
    __shared__ __align__(16) __half As[2][128][40];
    __shared__ __align__(16) __half Bs[2][32][136];
    __shared__ __align__(16) float  scr[8][16][20];

    const int m0 = blockIdx.x * 128;
    const int w  = blockIdx.y;
    const float* X = (m0 < MROWS / 2) ? xh + (size_t)m0 * EE
                                      : xb + (size_t)(m0 - MROWS / 2) * EE;
    const float* W  = (w == 0) ? Wk : ((w == 1) ? Wq : Wv);
    __half*     Out = (w == 0) ? g_K : ((w == 1) ? g_Q : g_V);

    const int tid = threadIdx.x, wid = tid >> 5, lane = tid & 31;
    const int warp_m = wid & 3, warp_n = wid >> 2;

    wmma::fragment<wmma::accumulator, 16, 16, 16, float> acc[2][4];
    #pragma unroll
    for (int i = 0; i < 2; i++)
        #pragma unroll
        for (int j = 0; j < 4; j++)
            wmma::fill_fragment(acc[i][j], 0.0f);

    const int rX = tid >> 3,  cX = (tid & 7) * 4;
    const int rW = tid >> 5,  cW = (tid & 31) * 4;

    #pragma unroll
    for (int i = 0; i < 4; i++) {
        float4 v = *(const float4*)&X[(size_t)(rX + i * 32) * EE + cX];
        __half2* d = (__half2*)&As[0][rX + i * 32][cX];
        d[0] = __floats2half2_rn(v.x, v.y);
        d[1] = __floats2half2_rn(v.z, v.w);
        float4 u = *(const float4*)&W[(size_t)(rW + i * 8) * HSZ + cW];
        __half2* e = (__half2*)&Bs[0][rW + i * 8][cW];
        e[0] = __floats2half2_rn(u.x, u.y);
        e[1] = __floats2half2_rn(u.z, u.w);
    }
    __syncthreads();

    for (int c = 0; c < 32; c++) {
        const int b = c & 1;
        float4 px[4], pw[4];
        if (c + 1 < 32) {
            #pragma unroll
            for (int i = 0; i < 4; i++) {
                px[i] = *(const float4*)&X[(size_t)(rX + i * 32) * EE +
                                           (c + 1) * 32 + cX];
                pw[i] = *(const float4*)&W[(size_t)((c + 1) * 32 + rW + i * 8) *
                                           HSZ + cW];
            }
        }
        #pragma unroll
        for (int kk = 0; kk < 32; kk += 16) {
            wmma::fragment<wmma::matrix_a, 16, 16, 16, __half,
                           wmma::row_major> a[2];
            wmma::fragment<wmma::matrix_b, 16, 16, 16, __half,
                           wmma::row_major> bf[4];
            #pragma unroll
            for (int i = 0; i < 2; i++)
                wmma::load_matrix_sync(a[i], &As[b][warp_m * 32 + i * 16][kk], 40);
            #pragma unroll
            for (int j = 0; j < 4; j++)
                wmma::load_matrix_sync(bf[j], &Bs[b][kk][warp_n * 64 + j * 16], 136);
            #pragma unroll
            for (int i = 0; i < 2; i++)
                #pragma unroll
                for (int j = 0; j < 4; j++)
                    wmma::mma_sync(acc[i][j], a[i], bf[j], acc[i][j]);
        }
        if (c + 1 < 32) {
            const int nb = (c + 1) & 1;
            #pragma unroll
            for (int i = 0; i < 4; i++) {
                __half2* d = (__half2*)&As[nb][rX + i * 32][cX];
                d[0] = __floats2half2_rn(px[i].x, px[i].y);
                d[1] = __floats2half2_rn(px[i].z, px[i].w);
                __half2* e = (__half2*)&Bs[nb][rW + i * 8][cW];
                e[0] = __floats2half2_rn(pw[i].x, pw[i].y);
                e[1] = __floats2half2_rn(pw[i].z, pw[i].w);
            }
        }
        __syncthreads();
    }

    const float sc = (w == 1) ? QSCALE : 1.0f;
    const int row = lane >> 1, c0 = (lane & 1) * 8;
    #pragma unroll
    for (int i = 0; i < 2; i++)
        #pragma unroll
        for (int j = 0; j < 4; j++) {
            __syncwarp();
            wmma::store_matrix_sync(&scr[wid][0][0], acc[i][j], 20,
                                    wmma::mem_row_major);
            __syncwarp();
            float4 u = *(float4*)&scr[wid][row][c0];
            float4 v = *(float4*)&scr[wid][row][c0 + 4];
            union { uint4 q; __half2 h[4]; } o;
            o.h[0] = __floats2half2_rn(u.x * sc, u.y * sc);
            o.h[1] = __floats2half2_rn(u.z * sc, u.w * sc);
            o.h[2] = __floats2half2_rn(v.x * sc, v.y * sc);
            o.h[3] = __floats2half2_rn(v.z * sc, v.w * sc);
            const int gm = m0 + warp_m * 32 + i * 16 + row;
            const int gc = warp_n * 64 + j * 16 + c0;
            *(uint4*)&Out[(size_t)gm * HSZ + gc] = o.q;
        }
}

// ============================================================================
// Fused flash attention v5: R11 warp algorithm, repacked as 128-thread CTAs
// (q-tile 64, 4 warps: warp_m=wid&1, warp_n=wid>>1), 2 CTAs/SM.
// smem: K[2]@0 V[2]@34816 Ph@69632 ([64][72] half) smLp@78848 ([64][2] f32)
// total 79360 -> two CTAs co-resident.
// ============================================================================
#define SM_K(b) ((b) * 17408)
#define SM_V(b) (34816 + (b) * 17408)
#define SM_PH   69632
#define SM_LP   78848
#define A_SMEM  79360

__global__ void __launch_bounds__(128, 2) attn_kernel(float* __restrict__ out)
{
    extern __shared__ __align__(16) char sm[];
    const uint32_t sa = smem_u32(sm);
    const uint32_t ph = sa + SM_PH;
    float* smLp = (float*)(sm + SM_LP);
    const int tid = threadIdx.x, wid = tid >> 5, lane = tid & 31;
    const int warp_m = wid & 1, warp_n = wid >> 1;
    const int tg = lane >> 2, tq = lane & 3;
    const int sb = blockIdx.y, q0 = blockIdx.x * 64;
    const __half* Qg = g_Q + ((size_t)sb * TT + q0) * HSZ;
    const __half* Kg = g_K + (size_t)sb * TT * HSZ;
    const __half* Vg = g_V + (size_t)sb * TT * HSZ;

    // prologue: chunk-0 K/V cp.async (64 rows x 256B each)
    #pragma unroll
    for (int t = 0; t < 8; t++) {
        int idx = tid + t * 128, r = idx >> 4, c16 = idx & 15;
        cp16(sa + SM_K(0) + r * 272 + c16 * 16,
             (const char*)Kg + (size_t)r * 256 + c16 * 16);
        cp16(sa + SM_V(0) + r * 272 + c16 * 16,
             (const char*)Vg + (size_t)r * 256 + c16 * 16);
    }
    CP_COMMIT();

    // hoist Q A-fragments: [2 m16][8 k16][4]
    uint32_t aq[2][8][4];
    #pragma unroll
    for (int i = 0; i < 2; i++)
        #pragma unroll
        for (int k = 0; k < 8; k++) {
            const __half* p = Qg + (size_t)(warp_m * 32 + i * 16 + tg) * HSZ +
                              k * 16 + tq * 2;
            aq[i][k][0] = *(const uint32_t*)p;
            aq[i][k][1] = *(const uint32_t*)(p + 8 * HSZ);
            aq[i][k][2] = *(const uint32_t*)(p + 8);
            aq[i][k][3] = *(const uint32_t*)(p + 8 * HSZ + 8);
        }

    float acc_o[2][8][4];
    #pragma unroll
    for (int i = 0; i < 2; i++)
        #pragma unroll
        for (int j = 0; j < 8; j++)
            #pragma unroll
            for (int e = 0; e < 4; e++)
                acc_o[i][j][e] = 0.0f;
    float Lc[4] = { 0.0f, 0.0f, 0.0f, 0.0f };

    const int l8 = lane & 7, sel = lane >> 3;
    const uint32_t koff = (uint32_t)((l8 + ((sel >> 1) & 1) * 8) * 272 +
                                     (sel & 1) * 16);
    const uint32_t voff = (uint32_t)((l8 + (sel & 1) * 8) * 272 +
                                     ((sel >> 1) & 1) * 16);
    const uint32_t poff = (uint32_t)((l8 + (sel & 1) * 8) * 144 +
                                     ((sel >> 1) & 1) * 16);

    for (int c = 0; c < 32; c++) {
        CP_WAIT(0);
        __syncthreads();
        if (c + 1 < 32) {
            const char* Kc = (const char*)Kg + (size_t)(c + 1) * 64 * 256;
            const char* Vc = (const char*)Vg + (size_t)(c + 1) * 64 * 256;
            #pragma unroll
            for (int t = 0; t < 8; t++) {
                int idx = tid + t * 128, r = idx >> 4, c16 = idx & 15;
                cp16(sa + SM_K((c + 1) & 1) + r * 272 + c16 * 16,
                     Kc + (size_t)r * 256 + c16 * 16);
                cp16(sa + SM_V((c + 1) & 1) + r * 272 + c16 * 16,
                     Vc + (size_t)r * 256 + c16 * 16);
            }
            CP_COMMIT();
        }
        const uint32_t kb = sa + SM_K(c & 1);
        const uint32_t vb = sa + SM_V(c & 1);

        // ---- S = Q K^T : warp tile 32x32 ----
        float acc_s[2][4][4];
        #pragma unroll
        for (int i = 0; i < 2; i++)
            #pragma unroll
            for (int j = 0; j < 4; j++)
                #pragma unroll
                for (int e = 0; e < 4; e++)
                    acc_s[i][j][e] = 0.0f;
        #pragma unroll
        for (int k = 0; k < 8; k++) {
            uint32_t bk[8];
            ldsm_x4(bk,     kb + (warp_n * 32) * 272 + k * 32 + koff);
            ldsm_x4(bk + 4, kb + (warp_n * 32 + 16) * 272 + k * 32 + koff);
            #pragma unroll
            for (int i = 0; i < 2; i++)
                #pragma unroll
                for (int j = 0; j < 4; j++)
                    mma16816(acc_s[i][j], aq[i][k], &bk[j * 2]);
        }

        // ---- P = exp2(S) in registers, fuse row sums ----
        uint32_t ap[2][2][4];
        #pragma unroll
        for (int i = 0; i < 2; i++)
            #pragma unroll
            for (int j = 0; j < 4; j++) {
                __half2 h0 = __floats2half2_rn(fexp2(acc_s[i][j][0]),
                                               fexp2(acc_s[i][j][1]));
                __half2 h1 = __floats2half2_rn(fexp2(acc_s[i][j][2]),
                                               fexp2(acc_s[i][j][3]));
                float2 f0 = __half22float2(h0);
                float2 f1 = __half22float2(h1);
                Lc[i * 2 + 0] += f0.x + f0.y;
                Lc[i * 2 + 1] += f1.x + f1.y;
                ap[i][j >> 1][(j & 1) * 2 + 0] = *(uint32_t*)&h0;
                ap[i][j >> 1][(j & 1) * 2 + 1] = *(uint32_t*)&h1;
            }

        PAIR_BAR(1 + warp_m);

        #pragma unroll
        for (int i = 0; i < 2; i++)
            #pragma unroll
            for (int j = 0; j < 4; j++) {
                uint32_t addr = ph + (uint32_t)(warp_m * 32 + i * 16 + tg) * 144 +
                                (uint32_t)(warp_n * 32 + j * 8 + tq * 2) * 2;
                asm volatile("st.shared.b32 [%0], %1;"
                             :: "r"(addr), "r"(ap[i][j >> 1][(j & 1) * 2]));
                asm volatile("st.shared.b32 [%0], %1;"
                             :: "r"(addr + 8 * 144),
                                "r"(ap[i][j >> 1][(j & 1) * 2 + 1]));
            }

        PAIR_BAR(1 + warp_m);

        // ---- O += P V : warp tile 32x64 ----
        #pragma unroll
        for (int s = 0; s < 4; s++) {
            uint32_t av[2][4];
            if ((s >> 1) == warp_n) {
                #pragma unroll
                for (int i = 0; i < 2; i++)
                    #pragma unroll
                    for (int e = 0; e < 4; e++)
                        av[i][e] = ap[i][s & 1][e];
            } else {
                #pragma unroll
                for (int i = 0; i < 2; i++)
                    ldsm_x4(av[i], ph + (uint32_t)(warp_m * 32 + i * 16) * 144 +
                                   s * 32 + poff);
            }
            #pragma unroll
            for (int jj = 0; jj < 4; jj++) {
                uint32_t bv[4];
                ldsm_x4_t(bv, vb + (s * 16) * 272 +
                              (warp_n * 64 + jj * 16) * 2 + voff);
                #pragma unroll
                for (int i = 0; i < 2; i++) {
                    mma16816(acc_o[i][jj * 2],     av[i], bv);
                    mma16816(acc_o[i][jj * 2 + 1], av[i], bv + 2);
                }
            }
        }
    }

    // ---- row sums ----
    #pragma unroll
    for (int q = 0; q < 4; q++) {
        Lc[q] += __shfl_xor_sync(0xffffffffu, Lc[q], 1);
        Lc[q] += __shfl_xor_sync(0xffffffffu, Lc[q], 2);
    }
    if (tq == 0) {
        #pragma unroll
        for (int i = 0; i < 2; i++)
            #pragma unroll
            for (int h = 0; h < 2; h++)
                smLp[(warp_m * 32 + i * 16 + h * 8 + tg) * 2 + warp_n] =
                    Lc[i * 2 + h];
    }
    __syncthreads();

    // ---- epilogue: O / L from registers ----
    #pragma unroll
    for (int i = 0; i < 2; i++) {
        const int r0 = warp_m * 32 + i * 16 + tg;
        const float inv0 = 1.0f / (smLp[r0 * 2] + smLp[r0 * 2 + 1]);
        const float inv1 = 1.0f / (smLp[(r0 + 8) * 2] + smLp[(r0 + 8) * 2 + 1]);
        float* O0 = out + ((size_t)sb * TT + q0 + r0) * HSZ + warp_n * 64 + tq * 2;
        float* O1 = O0 + 8 * HSZ;
        #pragma unroll
        for (int j = 0; j < 8; j++) {
            float2 v0 = { acc_o[i][j][0] * inv0, acc_o[i][j][1] * inv0 };
            float2 v1 = { acc_o[i][j][2] * inv1, acc_o[i][j][3] * inv1 };
            *(float2*)(O0 + j * 8) = v0;
            *(float2*)(O1 + j * 8) = v1;
        }
    }
}

// ============================================================================
extern "C" void kernel_launch(void* const* d_in, const int* in_sizes, int n_in,
                              void* d_out, int out_size)
{
    const float* x_head = (const float*)d_in[0];
    const float* x_body = (const float*)d_in[1];
    const float* Wk     = (const float*)d_in[2];
    const float* Wq     = (const float*)d_in[3];
    const float* Wv     = (const float*)d_in[4];
    float* out = (float*)d_out;

    cudaFuncSetAttribute(attn_kernel,
                         cudaFuncAttributeMaxDynamicSharedMemorySize, A_SMEM);

    proj_kernel<<<dim3(MROWS / 128, 3, 1), 256>>>(x_head, x_body, Wk, Wq, Wv);
    attn_kernel<<<dim3(TT / 64, NBATCH, 1), 128, A_SMEM>>>(out);
}